// round 1
// baseline (speedup 1.0000x reference)
#include <cuda_runtime.h>

// BoxFilter fused separable 9x9 depthwise conv, fp32 NHWC.
// B=4, H=1080, W=1920, C=16 -> out [4, 1072, 1912, 16].
//
// One thread owns one float4 (4 channels) of one pixel column of a 112-pixel
// strip. Vertical 9-tap runs out of a rolling register window (each input
// element read from HBM exactly once). Vertical results are exchanged through
// a double-buffered shared row (one __syncthreads per row), then the 9-tap
// horizontal pass reads taps from smem and stores the output. Packed
// fma.rn.f32x2 halves FMA instruction count.

namespace {
constexpr int KS       = 9;
constexpr int Hh       = 1080;
constexpr int Ww       = 1920;
constexpr int Cc       = 16;
constexpr int OH       = 1072;       // H - 8
constexpr int OW       = 1912;       // W - 8
constexpr int EXT_PX   = 112;        // strip width incl. horizontal halo
constexpr int OUT_PX   = 104;        // output pixels per strip
constexpr int NTH      = EXT_PX * 4; // 448 threads (4 float4-quads per pixel)
constexpr int GRID_X   = 19;         // ceil(1912/104), last tile overlapped
constexpr int GRID_Y   = 8;
constexpr int ROWS_PB  = OH / GRID_Y;       // 134 output rows per block
constexpr int IN_ROW_U2  = Ww * Cc / 4;     // 7680 ulonglong2 per input row
constexpr int OUT_ROW_U2 = OW * Cc / 4;     // 7648 ulonglong2 per output row
}

typedef unsigned long long u64;

// packed 2xfp32 fma: d = a*b + d
__device__ __forceinline__ void fma2(u64 &d, const u64 a, const u64 b) {
    asm("fma.rn.f32x2 %0, %1, %2, %0;" : "+l"(d) : "l"(a), "l"(b));
}

__global__ void __launch_bounds__(NTH, 1)
box_kernel(const float* __restrict__ xg, const float* __restrict__ wyg,
           const float* __restrict__ wxg, float* __restrict__ og)
{
    __shared__ ulonglong2 sb[2][NTH];   // double-buffered vertical-result row

    const int tid = threadIdx.x;
    const int q   = tid & 3;        // which float4 of the 16 channels
    const int pl  = tid >> 2;       // pixel within strip, 0..111

    const int bx = blockIdx.x, by = blockIdx.y, b = blockIdx.z;
    // Overlap the last tile so no access is ever out of bounds in x.
    const int px0 = min(bx * OUT_PX, OW - OUT_PX);
    const int r0  = by * ROWS_PB;

    // Per-channel weights: wy/wx are [9,16] floats; this thread needs the
    // float4 at channel 4q of each tap.
    ulonglong2 wyr[KS], wxr[KS];
    const ulonglong2* wyv = reinterpret_cast<const ulonglong2*>(wyg);
    const ulonglong2* wxv = reinterpret_cast<const ulonglong2*>(wxg);
    #pragma unroll
    for (int k = 0; k < KS; ++k) {
        wyr[k] = wyv[k * 4 + q];
        wxr[k] = wxv[k * 4 + q];
    }

    const ulonglong2* ip = reinterpret_cast<const ulonglong2*>(xg)
        + (size_t)(b * Hh + r0) * IN_ROW_U2 + (px0 + pl) * 4 + q;

    const bool emit = (pl < OUT_PX);
    ulonglong2* op = reinterpret_cast<ulonglong2*>(og)
        + (size_t)(b * OH + r0) * OUT_ROW_U2 + (px0 + pl) * 4 + q;

    // Prime rolling window with input rows r0 .. r0+7, cur = r0+8.
    ulonglong2 win[8], cur;
    #pragma unroll
    for (int k = 0; k < 8; ++k) { win[k] = *ip; ip += IN_ROW_U2; }
    cur = *ip; ip += IN_ROW_U2;

    for (int row = 0; row < ROWS_PB; ++row) {
        // Prefetch next input row early (hides HBM latency behind this row).
        ulonglong2 nxt = cur;
        if (row + 1 < ROWS_PB) nxt = *ip;
        ip += IN_ROW_U2;

        // Vertical 9-tap from register window.
        ulonglong2 acc; acc.x = 0ull; acc.y = 0ull;
        #pragma unroll
        for (int k = 0; k < 8; ++k) {
            fma2(acc.x, wyr[k].x, win[k].x);
            fma2(acc.y, wyr[k].y, win[k].y);
        }
        fma2(acc.x, wyr[8].x, cur.x);
        fma2(acc.y, wyr[8].y, cur.y);

        sb[row & 1][tid] = acc;
        __syncthreads();

        // Horizontal 9-tap from smem (taps are this column +4*j float4s).
        if (emit) {
            ulonglong2 o; o.x = 0ull; o.y = 0ull;
            const ulonglong2* s = &sb[row & 1][tid];
            #pragma unroll
            for (int j = 0; j < KS; ++j) {
                ulonglong2 t = s[4 * j];
                fma2(o.x, wxr[j].x, t.x);
                fma2(o.y, wxr[j].y, t.y);
            }
            *op = o;
        }
        op += OUT_ROW_U2;

        // Slide the vertical window down one row.
        #pragma unroll
        for (int k = 0; k < 7; ++k) win[k] = win[k + 1];
        win[7] = cur;
        cur = nxt;
    }
}

extern "C" void kernel_launch(void* const* d_in, const int* in_sizes, int n_in,
                              void* d_out, int out_size)
{
    const float* x  = (const float*)d_in[0];
    const float* wy = (const float*)d_in[1];
    const float* wx = (const float*)d_in[2];
    float* out = (float*)d_out;

    dim3 grid(GRID_X, GRID_Y, 4);
    dim3 block(NTH);
    box_kernel<<<grid, block>>>(x, wy, wx, out);
}

// round 2
// speedup vs baseline: 1.1436x; 1.1436x over previous
#include <cuda_runtime.h>

// BoxFilter fused separable 9x9 depthwise conv, fp32 NHWC.
// B=4, H=1080, W=1920, C=16 -> out [4, 1072, 1912, 16].
//
// Round-2 changes vs round 1 (which was occupancy-bound at 128 regs, 1
// block/SM, 21.9% occ):
//  * weights moved from registers to shared memory (-72 regs)
//  * 256-thread blocks with __launch_bounds__(256,3) -> 3 blocks/SM, 24 warps
//  * 2 output rows per iteration: half the barriers, 4 independent FMA
//    accumulation chains, weight LDS amortized over 2 rows
//  * double-buffered 2-row smem tap buffer, 1 __syncthreads per 2 rows

namespace {
constexpr int KS       = 9;
constexpr int Hh       = 1080;
constexpr int Ww       = 1920;
constexpr int Cc       = 16;
constexpr int OH       = 1072;        // H - 8
constexpr int OW       = 1912;        // W - 8
constexpr int EXT_PX   = 64;          // strip width incl. horizontal halo
constexpr int OUT_PX   = 56;          // output pixels per strip
constexpr int NTH      = EXT_PX * 4;  // 256 threads (4 float4-quads per pixel)
constexpr int GRID_X   = 35;          // ceil(1912/56), last tile overlapped
constexpr int GRID_Y   = 8;
constexpr int ROWS_PB  = OH / GRID_Y;       // 134 output rows per block
constexpr int ITERS    = ROWS_PB / 2;       // 67 two-row iterations
constexpr int IN_ROWS  = ROWS_PB + 8;       // 142 input rows touched
constexpr int IN_ROW_U2  = Ww * Cc / 4;     // 7680 ulonglong2 per input row
constexpr int OUT_ROW_U2 = OW * Cc / 4;     // 7648 ulonglong2 per output row
}

typedef unsigned long long u64;

// packed 2xfp32 fma: d = a*b + d
__device__ __forceinline__ void fma2(u64 &d, const u64 a, const u64 b) {
    asm("fma.rn.f32x2 %0, %1, %2, %0;" : "+l"(d) : "l"(a), "l"(b));
}

__global__ void __launch_bounds__(NTH, 3)
box_kernel(const float* __restrict__ xg, const float* __restrict__ wyg,
           const float* __restrict__ wxg, float* __restrict__ og)
{
    __shared__ ulonglong2 wy_s[KS * 4];      // [tap][quad], 16B each
    __shared__ ulonglong2 wx_s[KS * 4];
    __shared__ ulonglong2 sb[2][2][NTH];     // [buf][row-of-pair][col]

    const int tid = threadIdx.x;
    const int q   = tid & 3;        // which float4 of the 16 channels
    const int pl  = tid >> 2;       // pixel within strip, 0..63

    const int bx = blockIdx.x, by = blockIdx.y, b = blockIdx.z;
    // Overlap the last tile so no access is ever out of bounds in x.
    const int px0 = min(bx * OUT_PX, OW - OUT_PX);
    const int r0  = by * ROWS_PB;

    // Stage weights in smem (layout [k*4 + q], matching global).
    const ulonglong2* wyv = reinterpret_cast<const ulonglong2*>(wyg);
    const ulonglong2* wxv = reinterpret_cast<const ulonglong2*>(wxg);
    if (tid < KS * 4)                    wy_s[tid]      = wyv[tid];
    else if (tid >= 64 && tid < 64 + 36) wx_s[tid - 64] = wxv[tid - 64];

    const ulonglong2* ip = reinterpret_cast<const ulonglong2*>(xg)
        + (size_t)(b * Hh + r0) * IN_ROW_U2 + (px0 + pl) * 4 + q;

    const bool emit = (pl < OUT_PX);
    ulonglong2* op = reinterpret_cast<ulonglong2*>(og)
        + (size_t)(b * OH + r0) * OUT_ROW_U2 + (px0 + pl) * 4 + q;

    // Prime rolling window with input rows 0..7; cur = row 8, nxt = row 9.
    ulonglong2 win[8], cur, nxt;
    #pragma unroll
    for (int k = 0; k < 8; ++k) { win[k] = *ip; ip += IN_ROW_U2; }
    cur = *ip; ip += IN_ROW_U2;
    nxt = *ip; ip += IN_ROW_U2;

    __syncthreads();   // weights visible

    for (int i = 0; i < ITERS; ++i) {
        // Prefetch input rows 2i+10, 2i+11 (consumed next iteration).
        ulonglong2 p0 = cur, p1 = cur;
        if (2 * i + 10 < IN_ROWS) p0 = ip[0];
        if (2 * i + 11 < IN_ROWS) p1 = ip[IN_ROW_U2];
        ip += 2 * IN_ROW_U2;

        // Vertical 9-tap for output rows 2i and 2i+1 from register window.
        u64 a0x = 0, a0y = 0, a1x = 0, a1y = 0;
        #pragma unroll
        for (int k = 0; k < KS; ++k) {
            const ulonglong2 w  = wy_s[k * 4 + q];
            const ulonglong2 r0v = (k < 8) ? win[k] : cur;
            const ulonglong2 r1v = (k < 7) ? win[k + 1] : ((k == 7) ? cur : nxt);
            fma2(a0x, w.x, r0v.x); fma2(a0y, w.y, r0v.y);
            fma2(a1x, w.x, r1v.x); fma2(a1y, w.y, r1v.y);
        }

        const int buf = i & 1;
        { ulonglong2 v; v.x = a0x; v.y = a0y; sb[buf][0][tid] = v; }
        { ulonglong2 v; v.x = a1x; v.y = a1y; sb[buf][1][tid] = v; }
        __syncthreads();

        // Horizontal 9-tap from smem for both rows.
        if (emit) {
            u64 o0x = 0, o0y = 0, o1x = 0, o1y = 0;
            const ulonglong2* s0 = &sb[buf][0][tid];
            const ulonglong2* s1 = &sb[buf][1][tid];
            #pragma unroll
            for (int j = 0; j < KS; ++j) {
                const ulonglong2 w  = wx_s[j * 4 + q];
                const ulonglong2 t0 = s0[4 * j];
                const ulonglong2 t1 = s1[4 * j];
                fma2(o0x, w.x, t0.x); fma2(o0y, w.y, t0.y);
                fma2(o1x, w.x, t1.x); fma2(o1y, w.y, t1.y);
            }
            ulonglong2 v0; v0.x = o0x; v0.y = o0y;
            ulonglong2 v1; v1.x = o1x; v1.y = o1y;
            op[0]          = v0;
            op[OUT_ROW_U2] = v1;
        }
        op += 2 * OUT_ROW_U2;

        // Slide the vertical window down two rows.
        #pragma unroll
        for (int k = 0; k < 6; ++k) win[k] = win[k + 2];
        win[6] = cur; win[7] = nxt;
        cur = p0; nxt = p1;
    }
}

extern "C" void kernel_launch(void* const* d_in, const int* in_sizes, int n_in,
                              void* d_out, int out_size)
{
    const float* x  = (const float*)d_in[0];
    const float* wy = (const float*)d_in[1];
    const float* wx = (const float*)d_in[2];
    float* out = (float*)d_out;

    dim3 grid(GRID_X, GRID_Y, 4);
    dim3 block(NTH);
    box_kernel<<<grid, block>>>(x, wy, wx, out);
}